// round 11
// baseline (speedup 1.0000x reference)
#include <cuda_runtime.h>

#define WIN 32                       // live window: rho <= 0.65 (measured) =>
                                     // truncation ~1e-6, vs 1e-3 budget
#define WIN_PAIRS (WIN / 2)          // 16
#define T_HEAD (1024 - WIN)          // 992
#define NBLK 128                     // ONE WAVE on 148 SMs
#define NTHR 256
#define FULLM 0xffffffffu
#define FIXED_ITERS 12               // K error floor reached by t~10-12
                                     // (R8 exit t~10-12 == R9 16-iter rel_err)

__device__ __forceinline__ float rcp_fast(float x) {
    float r; asm("rcp.approx.f32 %0, %1;" : "=f"(r) : "f"(x)); return r;
}

// Single fused kernel, one block barrier, one wave. 128 blocks x 256 threads;
// each warp handles 4 sequences (lanes 0-15: base,base+2; 16-31: base+1,+3).
// Q/R LDG first; z prefetch hides under warp 0's lane-parallel Riccati
// (12 fully unrolled check-free iterations). The fast path (squarings + W
// build + sW write) runs UNCONDITIONALLY; the convergence verification is
// checked after, and on failure the checking loop + exact-window fallback
// recompute and overwrite sW before the barrier.
__global__ void __launch_bounds__(NTHR) kf_fused(const float* __restrict__ hist,
                                                 const float* __restrict__ Qlog,
                                                 const float* __restrict__ Rlog,
                                                 float* __restrict__ out) {
    __shared__ float sW[WIN_PAIRS * 17];   // [pair][16 w + pad]
    __shared__ float sApow[5][16];         // Ainf^(2^k), k = 0..4
    __shared__ float sAwin[WIN * 16];      // fallback scratch
    __shared__ float sKwin[WIN * 8];

    int tid = threadIdx.x, warp = tid >> 5, lane = tid & 31;

    // Critical-chain load first: Q/R for warp 0.
    float qr = 0.f;
    if (tid < 20) qr = (tid < 16) ? Qlog[tid] : Rlog[tid - 16];

    int base = (blockIdx.x * 8 + warp) * 4;
    int p16 = lane & 15;
    int s1 = base + ((lane < 16) ? 0 : 1);
    int s2 = s1 + 2;
    // Window = steps [992,1024) = float4 pairs [496,512).
    const float4* r1 = reinterpret_cast<const float4*>(hist) + (size_t)s1 * 512;
    const float4* r2 = reinterpret_cast<const float4*>(hist) + (size_t)s2 * 512;
    float4 z1 = r1[496 + p16];
    float4 z2 = r2[496 + p16];

    if (warp == 0) {
        int li = p16 >> 2, lj = p16 & 3;

        float qv = __expf(qr);
        if (lane == 0 || lane == 5 || lane == 10 || lane == 15 ||
            lane == 16 || lane == 19)
            qv += 1e-6f;
        float R0 = __shfl_sync(FULLM, qv, 16);
        float R1 = __shfl_sync(FULLM, qv, 17);
        float R2 = __shfl_sync(FULLM, qv, 18);
        float R3 = __shfl_sync(FULLM, qv, 19);
        float q  = __shfl_sync(FULLM, qv, p16);  // lanes 16-31 mirror 0-15

        float mi  = (li < 2) ? 1.f : 0.f;
        float mj  = (lj < 2) ? 1.f : 0.f;
        float mij = mi * mj;
        int src1 = (((li + 2) & 3) << 2) | lj;
        int src2 = (li << 2) | ((lj + 2) & 3);
        int src3 = (((li + 2) & 3) << 2) | ((lj + 2) & 3);

        float p = (li == lj) ? 1000.f : 0.f;   // P0 = 1000*I
        float kn0 = 0.f, kn1 = 0.f;            // NEGATED gain, row li

        auto step = [&]() {
            float t1 = __shfl_sync(FULLM, p, src1);
            float t2 = __shfl_sync(FULLM, p, src2);
            float t3 = __shfl_sync(FULLM, p, src3);
            float pp = fmaf(mi, t1, p + q);
            pp = fmaf(mj, t2, pp);
            pp = fmaf(mij, t3, pp);
            float pp00 = __shfl_sync(FULLM, pp, 0);
            float pp01 = __shfl_sync(FULLM, pp, 1);
            float pp10 = __shfl_sync(FULLM, pp, 4);
            float pp11 = __shfl_sync(FULLM, pp, 5);
            float ppi0 = __shfl_sync(FULLM, pp, li << 2);
            float ppi1 = __shfl_sync(FULLM, pp, (li << 2) | 1);
            float pp0j = __shfl_sync(FULLM, pp, lj);
            float pp1j = __shfl_sync(FULLM, pp, 4 | lj);
            float s00 = pp00 + R0, s01 = pp01 + R1;
            float s10 = pp10 + R2, s11 = pp11 + R3;
            float id = rcp_fast(fmaf(s00, s11, -s01 * s10));
            float j00 = -s11 * id, j01 = s01 * id;
            float j10 =  s10 * id, j11 = -s00 * id;
            kn0 = fmaf(ppi0, j00, ppi1 * j10);   // -K(li,0)
            kn1 = fmaf(ppi0, j01, ppi1 * j11);   // -K(li,1)
            p = fmaf(kn0, pp0j, fmaf(kn1, pp1j, pp));
        };

        // 11 unrolled check-free steps, then the 12th (delta recorded).
#pragma unroll
        for (int t = 0; t < FIXED_ITERS - 1; t++) step();
        float k0p = kn0, k1p = kn1;
        step();

        auto lane_A = [&](float k0, float k1) {
            float b = (lj & 1) ? k1 : k0;
            float d1 = (((lj & 1) ? (li == 1) : (li == 0))) ? 1.f : 0.f;
            float d2 = (lj >= 2 && li == lj) ? 1.f : 0.f;
            return b + d1 + d2;
        };

        // ---- Fast path, UNCONDITIONAL (verify checked after) ----
        {
            float V[8];
#pragma unroll
            for (int i = 0; i < 4; i++) {
                V[i * 2 + 0] = -__shfl_sync(FULLM, kn0, i << 2);
                V[i * 2 + 1] = -__shfl_sync(FULLM, kn1, i << 2);
            }
            float a = lane_A(kn0, kn1);
            if (lane < 16) sApow[0][lane] = a;
#pragma unroll
            for (int k = 1; k < 5; k++) {
                float c = 0.0f;
#pragma unroll
                for (int m = 0; m < 4; m++) {
                    float rim = __shfl_sync(FULLM, a, li * 4 + m);
                    float rmj = __shfl_sync(FULLM, a, m * 4 + lj);
                    c = fmaf(rim, rmj, c);
                }
                a = c;
                if (lane < 16) sApow[k][lane] = a;
            }
            __syncwarp();
            // Lane n -> W for exponent n (step 1023-n, tw = 31-n).
            int n = lane;
#pragma unroll
            for (int k = 0; k < 5; k++) {
                if ((n >> k) & 1) {
                    const float* M = sApow[k];
                    float Vn[8];
#pragma unroll
                    for (int i = 0; i < 4; i++) {
#pragma unroll
                        for (int c = 0; c < 2; c++) {
                            float s = M[i * 4 + 0] * V[0 * 2 + c];
                            s = fmaf(M[i * 4 + 1], V[1 * 2 + c], s);
                            s = fmaf(M[i * 4 + 2], V[2 * 2 + c], s);
                            s = fmaf(M[i * 4 + 3], V[3 * 2 + c], s);
                            Vn[i * 2 + c] = s;
                        }
                    }
#pragma unroll
                    for (int s = 0; s < 8; s++) V[s] = Vn[s];
                }
            }
            int tw = 31 - n;
            int pw = tw >> 1, sub = tw & 1;      // (992+tw)&1 == tw&1
#pragma unroll
            for (int s = 0; s < 8; s++) sW[pw * 17 + sub * 8 + s] = V[s];
        }

        // ---- Verification (off the fast-path chain) ----
        float dd = fmaxf(fabsf(kn0 - k0p), fabsf(kn1 - k1p));
        float km = fmaxf(fabsf(kn0), fabsf(kn1));
        bool ok = (dd <= fmaf(3e-4f, km, 1e-9f));

        if (!__all_sync(FULLM, ok)) {
            // Rare path: keep stepping with checks, then exact window +
            // backward suffix; overwrites sW before the block barrier.
            int conv = 0;
            for (int t = FIXED_ITERS; t < T_HEAD; t++) {
                k0p = kn0; k1p = kn1;
                step();
                float d2 = fmaxf(fabsf(kn0 - k0p), fabsf(kn1 - k1p));
                float k2 = fmaxf(fabsf(kn0), fabsf(kn1));
                bool o2 = (d2 <= fmaf(3e-4f, k2, 1e-9f));
                if (__all_sync(FULLM, o2)) { conv = 1; break; }
            }
            if (conv) {
                // Converged late: redo fast path with the settled gain.
                float V[8];
#pragma unroll
                for (int i = 0; i < 4; i++) {
                    V[i * 2 + 0] = -__shfl_sync(FULLM, kn0, i << 2);
                    V[i * 2 + 1] = -__shfl_sync(FULLM, kn1, i << 2);
                }
                float a = lane_A(kn0, kn1);
                if (lane < 16) sApow[0][lane] = a;
#pragma unroll
                for (int k = 1; k < 5; k++) {
                    float c = 0.0f;
#pragma unroll
                    for (int m = 0; m < 4; m++) {
                        float rim = __shfl_sync(FULLM, a, li * 4 + m);
                        float rmj = __shfl_sync(FULLM, a, m * 4 + lj);
                        c = fmaf(rim, rmj, c);
                    }
                    a = c;
                    if (lane < 16) sApow[k][lane] = a;
                }
                __syncwarp();
                int n = lane;
#pragma unroll
                for (int k = 0; k < 5; k++) {
                    if ((n >> k) & 1) {
                        const float* M = sApow[k];
                        float Vn[8];
#pragma unroll
                        for (int i = 0; i < 4; i++) {
#pragma unroll
                            for (int c = 0; c < 2; c++) {
                                float s = M[i * 4 + 0] * V[0 * 2 + c];
                                s = fmaf(M[i * 4 + 1], V[1 * 2 + c], s);
                                s = fmaf(M[i * 4 + 2], V[2 * 2 + c], s);
                                s = fmaf(M[i * 4 + 3], V[3 * 2 + c], s);
                                Vn[i * 2 + c] = s;
                            }
                        }
#pragma unroll
                        for (int s = 0; s < 8; s++) V[s] = Vn[s];
                    }
                }
                int tw = 31 - n;
                int pw = tw >> 1, sub = tw & 1;
#pragma unroll
                for (int s = 0; s < 8; s++) sW[pw * 17 + sub * 8 + s] = V[s];
            } else {
                // Never converged: exact lane-parallel window steps.
                for (int tw = 0; tw < WIN; tw++) {
                    step();
                    if (lane < 16) {
                        sAwin[tw * 16 + lane] = lane_A(kn0, kn1);
                        if (lj == 0) {
                            sKwin[tw * 8 + li * 2 + 0] = -kn0;
                            sKwin[tw * 8 + li * 2 + 1] = -kn1;
                        }
                    }
                }
                __syncwarp();
                if (lane == 0) {
                    float S[16];
#pragma unroll
                    for (int s = 0; s < 16; s++) S[s] = (s % 5 == 0) ? 1.0f : 0.0f;
                    for (int tw = WIN - 1; tw >= 0; tw--) {
                        const float* K = &sKwin[tw * 8];
                        float V[8];
#pragma unroll
                        for (int i = 0; i < 4; i++) {
#pragma unroll
                            for (int c = 0; c < 2; c++) {
                                float s = S[i * 4 + 0] * K[0 * 2 + c];
                                s = fmaf(S[i * 4 + 1], K[1 * 2 + c], s);
                                s = fmaf(S[i * 4 + 2], K[2 * 2 + c], s);
                                s = fmaf(S[i * 4 + 3], K[3 * 2 + c], s);
                                V[i * 2 + c] = s;
                            }
                        }
                        int pw = tw >> 1, sub = tw & 1;
#pragma unroll
                        for (int s = 0; s < 8; s++) sW[pw * 17 + sub * 8 + s] = V[s];
                        const float* Aw = &sAwin[tw * 16];
                        float Sn[16];
#pragma unroll
                        for (int i = 0; i < 4; i++) {
#pragma unroll
                            for (int c = 0; c < 4; c++) {
                                float s = S[i * 4 + 0] * Aw[0 * 4 + c];
                                s = fmaf(S[i * 4 + 1], Aw[1 * 4 + c], s);
                                s = fmaf(S[i * 4 + 2], Aw[2 * 4 + c], s);
                                s = fmaf(S[i * 4 + 3], Aw[3 * 4 + c], s);
                                Sn[i * 4 + c] = s;
                            }
                        }
#pragma unroll
                        for (int s = 0; s < 16; s++) S[s] = Sn[s];
                    }
                }
            }
        }
    }
    __syncthreads();   // single block barrier

    // Weighted sum: lane handles pair p16 for its TWO sequences (s1, s2).
    float a0 = 0.f, a1 = 0.f, a2 = 0.f, a3 = 0.f;   // s1
    float c0 = 0.f, c1 = 0.f, c2 = 0.f, c3 = 0.f;   // s2
    const float* w = &sW[p16 * 17];

    a0 = fmaf(w[0],  z1.x, a0); a0 = fmaf(w[1],  z1.y, a0);
    a1 = fmaf(w[2],  z1.x, a1); a1 = fmaf(w[3],  z1.y, a1);
    a2 = fmaf(w[4],  z1.x, a2); a2 = fmaf(w[5],  z1.y, a2);
    a3 = fmaf(w[6],  z1.x, a3); a3 = fmaf(w[7],  z1.y, a3);
    a0 = fmaf(w[8],  z1.z, a0); a0 = fmaf(w[9],  z1.w, a0);
    a1 = fmaf(w[10], z1.z, a1); a1 = fmaf(w[11], z1.w, a1);
    a2 = fmaf(w[12], z1.z, a2); a2 = fmaf(w[13], z1.w, a2);
    a3 = fmaf(w[14], z1.z, a3); a3 = fmaf(w[15], z1.w, a3);

    c0 = fmaf(w[0],  z2.x, c0); c0 = fmaf(w[1],  z2.y, c0);
    c1 = fmaf(w[2],  z2.x, c1); c1 = fmaf(w[3],  z2.y, c1);
    c2 = fmaf(w[4],  z2.x, c2); c2 = fmaf(w[5],  z2.y, c2);
    c3 = fmaf(w[6],  z2.x, c3); c3 = fmaf(w[7],  z2.y, c3);
    c0 = fmaf(w[8],  z2.z, c0); c0 = fmaf(w[9],  z2.w, c0);
    c1 = fmaf(w[10], z2.z, c1); c1 = fmaf(w[11], z2.w, c1);
    c2 = fmaf(w[12], z2.z, c2); c2 = fmaf(w[13], z2.w, c2);
    c3 = fmaf(w[14], z2.z, c3); c3 = fmaf(w[15], z2.w, c3);

    // 4-stage reduce keeps the 16-lane halves separate.
#pragma unroll
    for (int s = 8; s > 0; s >>= 1) {
        a0 += __shfl_xor_sync(FULLM, a0, s);
        a1 += __shfl_xor_sync(FULLM, a1, s);
        a2 += __shfl_xor_sync(FULLM, a2, s);
        a3 += __shfl_xor_sync(FULLM, a3, s);
        c0 += __shfl_xor_sync(FULLM, c0, s);
        c1 += __shfl_xor_sync(FULLM, c1, s);
        c2 += __shfl_xor_sync(FULLM, c2, s);
        c3 += __shfl_xor_sync(FULLM, c3, s);
    }

    if (p16 == 0) {   // lane 0 -> s1=base,s2=base+2; lane 16 -> base+1,base+3
        float* o1 = out + (size_t)s1 * 6;
        o1[0] = a0 + a2;            o1[1] = a1 + a3;
        o1[2] = fmaf(2.f, a2, a0);  o1[3] = fmaf(2.f, a3, a1);
        o1[4] = fmaf(3.f, a2, a0);  o1[5] = fmaf(3.f, a3, a1);
        float* o2 = out + (size_t)s2 * 6;
        o2[0] = c0 + c2;            o2[1] = c1 + c3;
        o2[2] = fmaf(2.f, c2, c0);  o2[3] = fmaf(2.f, c3, c1);
        o2[4] = fmaf(3.f, c2, c0);  o2[5] = fmaf(3.f, c3, c1);
    }
}

extern "C" void kernel_launch(void* const* d_in, const int* in_sizes, int n_in,
                              void* d_out, int out_size) {
    const float* hist = (const float*)d_in[0];
    const float* Qlog = (const float*)d_in[1];
    const float* Rlog = (const float*)d_in[2];
    float* out = (float*)d_out;

    kf_fused<<<NBLK, NTHR>>>(hist, Qlog, Rlog, out);
}

// round 12
// speedup vs baseline: 1.3140x; 1.3140x over previous
#include <cuda_runtime.h>

#define WIN 32                       // live window: rho <= 0.65 (measured) =>
                                     // truncation ~1e-6, vs 1e-3 budget
#define WIN_PAIRS (WIN / 2)          // 16
#define T_HEAD (1024 - WIN)          // 992
#define NBLK 128                     // ONE WAVE on 148 SMs
#define NTHR 256
#define FULLM 0xffffffffu
#define FIXED_ITERS 12               // R8 exit fired t~10-12 with identical
                                     // rel_err to 16 iters => floor reached

__device__ __forceinline__ float rcp_fast(float x) {
    float r; asm("rcp.approx.f32 %0, %1;" : "=f"(r) : "f"(x)); return r;
}

// R10 structure (known-best 6.62us, regs 48) with FIXED_ITERS 12 as the ONLY
// delta. Single fused kernel, one block barrier, one wave. 128 blocks x 256
// threads; each warp handles 4 sequences (lanes 0-15: base,base+2; 16-31:
// base+1,+3). Q/R LDG first; z prefetch hides under warp 0's lane-parallel
// Riccati (12 fully unrolled check-free iterations + single verification;
// checking-loop + exact-window fallback preserved). Then 4 shuffle squarings
// + 32-lane W build.
__global__ void __launch_bounds__(NTHR) kf_fused(const float* __restrict__ hist,
                                                 const float* __restrict__ Qlog,
                                                 const float* __restrict__ Rlog,
                                                 float* __restrict__ out) {
    __shared__ float sW[WIN_PAIRS * 17];   // [pair][16 w + pad]
    __shared__ float sApow[5][16];         // Ainf^(2^k), k = 0..4
    __shared__ float sAwin[WIN * 16];      // fallback scratch
    __shared__ float sKwin[WIN * 8];

    int tid = threadIdx.x, warp = tid >> 5, lane = tid & 31;

    // Critical-chain load first: Q/R for warp 0.
    float qr = 0.f;
    if (tid < 20) qr = (tid < 16) ? Qlog[tid] : Rlog[tid - 16];

    int base = (blockIdx.x * 8 + warp) * 4;
    int p16 = lane & 15;
    int s1 = base + ((lane < 16) ? 0 : 1);
    int s2 = s1 + 2;
    // Window = steps [992,1024) = float4 pairs [496,512).
    const float4* r1 = reinterpret_cast<const float4*>(hist) + (size_t)s1 * 512;
    const float4* r2 = reinterpret_cast<const float4*>(hist) + (size_t)s2 * 512;
    float4 z1 = r1[496 + p16];
    float4 z2 = r2[496 + p16];

    if (warp == 0) {
        int li = p16 >> 2, lj = p16 & 3;

        float qv = __expf(qr);
        if (lane == 0 || lane == 5 || lane == 10 || lane == 15 ||
            lane == 16 || lane == 19)
            qv += 1e-6f;
        float R0 = __shfl_sync(FULLM, qv, 16);
        float R1 = __shfl_sync(FULLM, qv, 17);
        float R2 = __shfl_sync(FULLM, qv, 18);
        float R3 = __shfl_sync(FULLM, qv, 19);
        float q  = __shfl_sync(FULLM, qv, p16);  // lanes 16-31 mirror 0-15

        float mi  = (li < 2) ? 1.f : 0.f;
        float mj  = (lj < 2) ? 1.f : 0.f;
        float mij = mi * mj;
        int src1 = (((li + 2) & 3) << 2) | lj;
        int src2 = (li << 2) | ((lj + 2) & 3);
        int src3 = (((li + 2) & 3) << 2) | ((lj + 2) & 3);

        float p = (li == lj) ? 1000.f : 0.f;   // P0 = 1000*I
        float kn0 = 0.f, kn1 = 0.f;            // NEGATED gain, row li

        // One Riccati step, branch-free.
        auto step = [&]() {
            float t1 = __shfl_sync(FULLM, p, src1);
            float t2 = __shfl_sync(FULLM, p, src2);
            float t3 = __shfl_sync(FULLM, p, src3);
            float pp = fmaf(mi, t1, p + q);
            pp = fmaf(mj, t2, pp);
            pp = fmaf(mij, t3, pp);
            float pp00 = __shfl_sync(FULLM, pp, 0);
            float pp01 = __shfl_sync(FULLM, pp, 1);
            float pp10 = __shfl_sync(FULLM, pp, 4);
            float pp11 = __shfl_sync(FULLM, pp, 5);
            float ppi0 = __shfl_sync(FULLM, pp, li << 2);
            float ppi1 = __shfl_sync(FULLM, pp, (li << 2) | 1);
            float pp0j = __shfl_sync(FULLM, pp, lj);
            float pp1j = __shfl_sync(FULLM, pp, 4 | lj);
            float s00 = pp00 + R0, s01 = pp01 + R1;
            float s10 = pp10 + R2, s11 = pp11 + R3;
            float id = rcp_fast(fmaf(s00, s11, -s01 * s10));
            float j00 = -s11 * id, j01 = s01 * id;
            float j10 =  s10 * id, j11 = -s00 * id;
            kn0 = fmaf(ppi0, j00, ppi1 * j10);   // -K(li,0)
            kn1 = fmaf(ppi0, j01, ppi1 * j11);   // -K(li,1)
            p = fmaf(kn0, pp0j, fmaf(kn1, pp1j, pp));
        };

        // 11 unrolled check-free steps, then the 12th + verify.
#pragma unroll
        for (int t = 0; t < FIXED_ITERS - 1; t++) step();
        float k0p = kn0, k1p = kn1;
        step();

        float dd = fmaxf(fabsf(kn0 - k0p), fabsf(kn1 - k1p));
        float km = fmaxf(fabsf(kn0), fabsf(kn1));
        bool ok = (dd <= fmaf(3e-4f, km, 1e-9f));
        int conv = __all_sync(FULLM, ok) ? 1 : 0;

        if (!conv) {
            for (int t = FIXED_ITERS; t < T_HEAD; t++) {
                k0p = kn0; k1p = kn1;
                step();
                float d2 = fmaxf(fabsf(kn0 - k0p), fabsf(kn1 - k1p));
                float k2 = fmaxf(fabsf(kn0), fabsf(kn1));
                bool o2 = (d2 <= fmaf(3e-4f, k2, 1e-9f));
                if (__all_sync(FULLM, o2)) { conv = 1; break; }
            }
        }

        auto lane_A = [&](float k0, float k1) {
            float b = (lj & 1) ? k1 : k0;
            float d1 = (((lj & 1) ? (li == 1) : (li == 0))) ? 1.f : 0.f;
            float d2 = (lj >= 2 && li == lj) ? 1.f : 0.f;
            return b + d1 + d2;
        };

        if (conv) {
            float V[8];
#pragma unroll
            for (int i = 0; i < 4; i++) {
                V[i * 2 + 0] = -__shfl_sync(FULLM, kn0, i << 2);
                V[i * 2 + 1] = -__shfl_sync(FULLM, kn1, i << 2);
            }
            float a = lane_A(kn0, kn1);
            if (lane < 16) sApow[0][lane] = a;
#pragma unroll
            for (int k = 1; k < 5; k++) {
                float c = 0.0f;
#pragma unroll
                for (int m = 0; m < 4; m++) {
                    float rim = __shfl_sync(FULLM, a, li * 4 + m);
                    float rmj = __shfl_sync(FULLM, a, m * 4 + lj);
                    c = fmaf(rim, rmj, c);
                }
                a = c;
                if (lane < 16) sApow[k][lane] = a;
            }
            __syncwarp();
            // Lane n -> W for exponent n (step 1023-n, tw = 31-n).
            int n = lane;
#pragma unroll
            for (int k = 0; k < 5; k++) {
                if ((n >> k) & 1) {
                    const float* M = sApow[k];
                    float Vn[8];
#pragma unroll
                    for (int i = 0; i < 4; i++) {
#pragma unroll
                        for (int c = 0; c < 2; c++) {
                            float s = M[i * 4 + 0] * V[0 * 2 + c];
                            s = fmaf(M[i * 4 + 1], V[1 * 2 + c], s);
                            s = fmaf(M[i * 4 + 2], V[2 * 2 + c], s);
                            s = fmaf(M[i * 4 + 3], V[3 * 2 + c], s);
                            Vn[i * 2 + c] = s;
                        }
                    }
#pragma unroll
                    for (int s = 0; s < 8; s++) V[s] = Vn[s];
                }
            }
            int tw = 31 - n;
            int pw = tw >> 1, sub = tw & 1;      // (992+tw)&1 == tw&1
#pragma unroll
            for (int s = 0; s < 8; s++) sW[pw * 17 + sub * 8 + s] = V[s];
        } else {
            // Fallback: WIN exact lane-parallel steps + backward suffix.
            for (int tw = 0; tw < WIN; tw++) {
                step();
                if (lane < 16) {
                    sAwin[tw * 16 + lane] = lane_A(kn0, kn1);
                    if (lj == 0) {
                        sKwin[tw * 8 + li * 2 + 0] = -kn0;
                        sKwin[tw * 8 + li * 2 + 1] = -kn1;
                    }
                }
            }
            __syncwarp();
            if (lane == 0) {
                float S[16];
#pragma unroll
                for (int s = 0; s < 16; s++) S[s] = (s % 5 == 0) ? 1.0f : 0.0f;
                for (int tw = WIN - 1; tw >= 0; tw--) {
                    const float* K = &sKwin[tw * 8];
                    float V[8];
#pragma unroll
                    for (int i = 0; i < 4; i++) {
#pragma unroll
                        for (int c = 0; c < 2; c++) {
                            float s = S[i * 4 + 0] * K[0 * 2 + c];
                            s = fmaf(S[i * 4 + 1], K[1 * 2 + c], s);
                            s = fmaf(S[i * 4 + 2], K[2 * 2 + c], s);
                            s = fmaf(S[i * 4 + 3], K[3 * 2 + c], s);
                            V[i * 2 + c] = s;
                        }
                    }
                    int pw = tw >> 1, sub = tw & 1;
#pragma unroll
                    for (int s = 0; s < 8; s++) sW[pw * 17 + sub * 8 + s] = V[s];
                    const float* Aw = &sAwin[tw * 16];
                    float Sn[16];
#pragma unroll
                    for (int i = 0; i < 4; i++) {
#pragma unroll
                        for (int c = 0; c < 4; c++) {
                            float s = S[i * 4 + 0] * Aw[0 * 4 + c];
                            s = fmaf(S[i * 4 + 1], Aw[1 * 4 + c], s);
                            s = fmaf(S[i * 4 + 2], Aw[2 * 4 + c], s);
                            s = fmaf(S[i * 4 + 3], Aw[3 * 4 + c], s);
                            Sn[i * 4 + c] = s;
                        }
                    }
#pragma unroll
                    for (int s = 0; s < 16; s++) S[s] = Sn[s];
                }
            }
        }
    }
    __syncthreads();   // single block barrier

    // Weighted sum: lane handles pair p16 for its TWO sequences (s1, s2).
    float a0 = 0.f, a1 = 0.f, a2 = 0.f, a3 = 0.f;   // s1
    float c0 = 0.f, c1 = 0.f, c2 = 0.f, c3 = 0.f;   // s2
    const float* w = &sW[p16 * 17];

    a0 = fmaf(w[0],  z1.x, a0); a0 = fmaf(w[1],  z1.y, a0);
    a1 = fmaf(w[2],  z1.x, a1); a1 = fmaf(w[3],  z1.y, a1);
    a2 = fmaf(w[4],  z1.x, a2); a2 = fmaf(w[5],  z1.y, a2);
    a3 = fmaf(w[6],  z1.x, a3); a3 = fmaf(w[7],  z1.y, a3);
    a0 = fmaf(w[8],  z1.z, a0); a0 = fmaf(w[9],  z1.w, a0);
    a1 = fmaf(w[10], z1.z, a1); a1 = fmaf(w[11], z1.w, a1);
    a2 = fmaf(w[12], z1.z, a2); a2 = fmaf(w[13], z1.w, a2);
    a3 = fmaf(w[14], z1.z, a3); a3 = fmaf(w[15], z1.w, a3);

    c0 = fmaf(w[0],  z2.x, c0); c0 = fmaf(w[1],  z2.y, c0);
    c1 = fmaf(w[2],  z2.x, c1); c1 = fmaf(w[3],  z2.y, c1);
    c2 = fmaf(w[4],  z2.x, c2); c2 = fmaf(w[5],  z2.y, c2);
    c3 = fmaf(w[6],  z2.x, c3); c3 = fmaf(w[7],  z2.y, c3);
    c0 = fmaf(w[8],  z2.z, c0); c0 = fmaf(w[9],  z2.w, c0);
    c1 = fmaf(w[10], z2.z, c1); c1 = fmaf(w[11], z2.w, c1);
    c2 = fmaf(w[12], z2.z, c2); c2 = fmaf(w[13], z2.w, c2);
    c3 = fmaf(w[14], z2.z, c3); c3 = fmaf(w[15], z2.w, c3);

    // 4-stage reduce keeps the 16-lane halves separate.
#pragma unroll
    for (int s = 8; s > 0; s >>= 1) {
        a0 += __shfl_xor_sync(FULLM, a0, s);
        a1 += __shfl_xor_sync(FULLM, a1, s);
        a2 += __shfl_xor_sync(FULLM, a2, s);
        a3 += __shfl_xor_sync(FULLM, a3, s);
        c0 += __shfl_xor_sync(FULLM, c0, s);
        c1 += __shfl_xor_sync(FULLM, c1, s);
        c2 += __shfl_xor_sync(FULLM, c2, s);
        c3 += __shfl_xor_sync(FULLM, c3, s);
    }

    if (p16 == 0) {   // lane 0 -> base/base+2, lane 16 -> base+1/base+3
        float* o1 = out + (size_t)s1 * 6;
        o1[0] = a0 + a2;            o1[1] = a1 + a3;
        o1[2] = fmaf(2.f, a2, a0);  o1[3] = fmaf(2.f, a3, a1);
        o1[4] = fmaf(3.f, a2, a0);  o1[5] = fmaf(3.f, a3, a1);
        float* o2 = out + (size_t)s2 * 6;
        o2[0] = c0 + c2;            o2[1] = c1 + c3;
        o2[2] = fmaf(2.f, c2, c0);  o2[3] = fmaf(2.f, c3, c1);
        o2[4] = fmaf(3.f, c2, c0);  o2[5] = fmaf(3.f, c3, c1);
    }
}

extern "C" void kernel_launch(void* const* d_in, const int* in_sizes, int n_in,
                              void* d_out, int out_size) {
    const float* hist = (const float*)d_in[0];
    const float* Qlog = (const float*)d_in[1];
    const float* Rlog = (const float*)d_in[2];
    float* out = (float*)d_out;

    kf_fused<<<NBLK, NTHR>>>(hist, Qlog, Rlog, out);
}